// round 1
// baseline (speedup 1.0000x reference)
#include <cuda_runtime.h>
#include <math.h>

#define BATCH 2
#define NTOK  2304
#define CDIM  768
#define NH    12
#define HD    64
#define HWID  48

// ---------------- scratch (static device allocations; no cudaMalloc) ----------
__device__ float g_Q[BATCH*NH*NTOK*HD];
__device__ float g_K[BATCH*NH*NTOK*HD];
__device__ float g_V[BATCH*NH*NTOK*HD];
__device__ float g_O[BATCH*NH*NTOK*HD];
__device__ float g_P[BATCH*NTOK*CDIM];
__device__ float g_pool[BATCH*2*NTOK];
__device__ float g_gate[BATCH*NTOK];

// ---------------- generic 64x64x16 SGEMM: C = A @ B^T + bias -------------------
// A: [M, 768] row-major (MODE 2 gathers A from g_O head layout)
// Bw: [Nout, 768] row-major (torch Linear weight)
// MODE 0: out -> g_Q[b,h,n,d]   (Nout=768)
// MODE 1: out -> g_K/g_V        (Nout=1536)
// MODE 2: A from g_O, out -> g_P[b,n,c] (Nout=768)
template<int MODE>
__global__ __launch_bounds__(256) void gemm_k(const float* __restrict__ A,
                                              const float* __restrict__ Bw,
                                              const float* __restrict__ bias)
{
    __shared__ __align__(16) float As[16][68];
    __shared__ __align__(16) float Bs[16][68];
    const int m0 = blockIdx.y * 64;
    const int n0 = blockIdx.x * 64;
    const int t  = threadIdx.x;
    const int tx = t & 15, ty = t >> 4;
    const int lcol = t & 15, lrow = t >> 4;

    float acc[4][4] = {};

    for (int k0 = 0; k0 < CDIM; k0 += 16) {
        #pragma unroll
        for (int p = 0; p < 4; p++) {
            int row = lrow + p * 16;
            int m = m0 + row;
            float va;
            if (MODE == 2) {
                int b = (m >= NTOK) ? 1 : 0;
                int n = m - b * NTOK;
                int kk2 = k0 + lcol;
                va = g_O[((b * NH + (kk2 >> 6)) * NTOK + n) * HD + (kk2 & 63)];
            } else {
                va = A[m * CDIM + k0 + lcol];
            }
            As[lcol][row] = va;
            Bs[lcol][row] = Bw[(n0 + row) * CDIM + k0 + lcol];
        }
        __syncthreads();
        #pragma unroll
        for (int kk = 0; kk < 16; kk++) {
            float4 a = *(const float4*)&As[kk][ty * 4];
            float4 b = *(const float4*)&Bs[kk][tx * 4];
            float av[4] = {a.x, a.y, a.z, a.w};
            float bv[4] = {b.x, b.y, b.z, b.w};
            #pragma unroll
            for (int i = 0; i < 4; i++)
                #pragma unroll
                for (int j = 0; j < 4; j++)
                    acc[i][j] += av[i] * bv[j];
        }
        __syncthreads();
    }

    #pragma unroll
    for (int i = 0; i < 4; i++) {
        int m = m0 + ty * 4 + i;
        int b = (m >= NTOK) ? 1 : 0;
        int n = m - b * NTOK;
        #pragma unroll
        for (int j = 0; j < 4; j++) {
            int o = n0 + tx * 4 + j;
            float v = acc[i][j] + bias[o];
            if (MODE == 0) {
                g_Q[((b * NH + (o >> 6)) * NTOK + n) * HD + (o & 63)] = v;
            } else if (MODE == 1) {
                int tsel = (o >= CDIM) ? 1 : 0;
                int r = o - tsel * CDIM;
                float* dst = tsel ? g_V : g_K;
                dst[((b * NH + (r >> 6)) * NTOK + n) * HD + (r & 63)] = v;
            } else {
                g_P[m * CDIM + o] = v;
            }
        }
    }
}

// ---------------- flash attention -------------------------------------------
// grid: (18 q-tiles of 128, 24 bh), 256 threads, 8x4 micro-tile.
// Unnormalized exp accumulation (logits are O(1): no max subtraction needed),
// final division by row sum. d-major (transposed) smem for float4 LDS in both
// the S (Q.K^T) and PV phases.
__global__ __launch_bounds__(256) void attn_k()
{
    extern __shared__ __align__(16) float sm[];
    float* Qst = sm;               // [64][132]  (d-major Q tile, 128 queries)
    float* Kst = Qst + 64 * 132;   // [64][68]   (d-major K tile, 64 keys)
    float* Vsm = Kst + 64 * 68;    // [64][68]   (j-major V tile)
    float* Pst = Vsm + 64 * 68;    // [64][132]  (j-major P tile)

    const int t  = threadIdx.x;
    const int tx = t & 15, ty = t >> 4;
    const int bh = blockIdx.y;
    const int q0 = blockIdx.x * 128;

    const float* Qh = g_Q + (size_t)bh * NTOK * HD;
    const float* Kh = g_K + (size_t)bh * NTOK * HD;
    const float* Vh = g_V + (size_t)bh * NTOK * HD;
    float*       Oh = g_O + (size_t)bh * NTOK * HD;

    // Load Q tile (transposed into d-major)
    #pragma unroll
    for (int p = 0; p < 32; p++) {
        int idx = t + p * 256;
        int i = idx >> 6, d = idx & 63;
        Qst[d * 132 + i] = Qh[(q0 + i) * HD + d];
    }

    float Oacc[8][4] = {};
    float lacc[8] = {};

    for (int k0 = 0; k0 < NTOK; k0 += 64) {
        __syncthreads();   // prior PV readers done before K/V overwrite
        #pragma unroll
        for (int p = 0; p < 16; p++) {
            int idx = t + p * 256;
            int j = idx >> 6, d = idx & 63;
            Kst[d * 68 + j] = Kh[(k0 + j) * HD + d];
        }
        #pragma unroll
        for (int p = 0; p < 4; p++) {
            int idx4 = t + p * 256;
            int j = idx4 >> 4, q4 = idx4 & 15;
            *(float4*)&Vsm[j * 68 + q4 * 4] =
                *(const float4*)&Vh[(k0 + j) * HD + q4 * 4];
        }
        __syncthreads();

        // S = Q K^T (8 rows x 4 cols per thread)
        float S[8][4] = {};
        #pragma unroll 8
        for (int d = 0; d < 64; d++) {
            float4 a0 = *(const float4*)&Qst[d * 132 + ty * 8];
            float4 a1 = *(const float4*)&Qst[d * 132 + ty * 8 + 4];
            float4 b  = *(const float4*)&Kst[d * 68 + tx * 4];
            float av[8] = {a0.x, a0.y, a0.z, a0.w, a1.x, a1.y, a1.z, a1.w};
            float bv[4] = {b.x, b.y, b.z, b.w};
            #pragma unroll
            for (int r = 0; r < 8; r++)
                #pragma unroll
                for (int c = 0; c < 4; c++)
                    S[r][c] += av[r] * bv[c];
        }

        // exp, accumulate row sums, write P (j-major)
        #pragma unroll
        for (int r = 0; r < 8; r++) {
            #pragma unroll
            for (int c = 0; c < 4; c++) {
                float pe = __expf(S[r][c] * 0.125f);
                lacc[r] += pe;
                Pst[(tx * 4 + c) * 132 + ty * 8 + r] = pe;
            }
        }
        __syncthreads();

        // O += P @ V
        #pragma unroll 8
        for (int j = 0; j < 64; j++) {
            float4 a0 = *(const float4*)&Pst[j * 132 + ty * 8];
            float4 a1 = *(const float4*)&Pst[j * 132 + ty * 8 + 4];
            float4 b  = *(const float4*)&Vsm[j * 68 + tx * 4];
            float av[8] = {a0.x, a0.y, a0.z, a0.w, a1.x, a1.y, a1.z, a1.w};
            float bv[4] = {b.x, b.y, b.z, b.w};
            #pragma unroll
            for (int r = 0; r < 8; r++)
                #pragma unroll
                for (int c = 0; c < 4; c++)
                    Oacc[r][c] += av[r] * bv[c];
        }
    }

    // reduce row sums across the 16 tx lanes (reuse Kst as scratch [128][17])
    __syncthreads();
    float* lp = Kst;
    #pragma unroll
    for (int r = 0; r < 8; r++) lp[(ty * 8 + r) * 17 + tx] = lacc[r];
    __syncthreads();
    #pragma unroll
    for (int r = 0; r < 8; r++) {
        float s = 0.f;
        #pragma unroll
        for (int u = 0; u < 16; u++) s += lp[(ty * 8 + r) * 17 + u];
        float inv = 1.0f / s;
        float4 o = make_float4(Oacc[r][0] * inv, Oacc[r][1] * inv,
                               Oacc[r][2] * inv, Oacc[r][3] * inv);
        *(float4*)&Oh[(q0 + ty * 8 + r) * HD + tx * 4] = o;
    }
}

// ---------------- channel pooling: avg & max over C per (b,n) ----------------
__global__ __launch_bounds__(256) void pool_k()
{
    int wid  = (blockIdx.x * 256 + threadIdx.x) >> 5;   // one warp per (b,n)
    int lane = threadIdx.x & 31;
    if (wid >= BATCH * NTOK) return;
    const float* row = g_P + (size_t)wid * CDIM;
    float s = 0.f, m = -INFINITY;
    #pragma unroll
    for (int i = 0; i < CDIM / 32; i++) {
        float v = row[lane + i * 32];
        s += v; m = fmaxf(m, v);
    }
    #pragma unroll
    for (int o = 16; o; o >>= 1) {
        s += __shfl_xor_sync(0xffffffffu, s, o);
        m = fmaxf(m, __shfl_xor_sync(0xffffffffu, m, o));
    }
    if (lane == 0) {
        int b = (wid >= NTOK) ? 1 : 0;
        int n = wid - b * NTOK;
        g_pool[(b * 2 + 0) * NTOK + n] = s * (1.0f / CDIM);
        g_pool[(b * 2 + 1) * NTOK + n] = m;
    }
}

// ---------------- 7x7x2 conv + sigmoid gate ----------------------------------
__global__ __launch_bounds__(256) void conv_k(const float* __restrict__ sa_w)
{
    int idx = blockIdx.x * 256 + threadIdx.x;
    if (idx >= BATCH * NTOK) return;
    int b = (idx >= NTOK) ? 1 : 0;
    int n = idx - b * NTOK;
    int hh = n / HWID, ww = n % HWID;
    float acc = 0.f;
    #pragma unroll
    for (int ch = 0; ch < 2; ch++) {
        const float* pp = g_pool + (b * 2 + ch) * NTOK;
        #pragma unroll
        for (int ki = 0; ki < 7; ki++) {
            int y = hh + ki - 3;
            if ((unsigned)y >= (unsigned)HWID) continue;
            #pragma unroll
            for (int kj = 0; kj < 7; kj++) {
                int x = ww + kj - 3;
                if ((unsigned)x >= (unsigned)HWID) continue;
                acc += sa_w[ch * 49 + ki * 7 + kj] * pp[y * HWID + x];
            }
        }
    }
    g_gate[idx] = 1.0f / (1.0f + __expf(-acc));
}

// ---------------- gate multiply into d_out ------------------------------------
__global__ __launch_bounds__(256) void gate_k(float* __restrict__ out)
{
    int idx = blockIdx.x * 256 + threadIdx.x;          // over float4 elems
    float4 v = ((const float4*)g_P)[idx];
    int row = idx / (CDIM / 4);                        // (b*N + n)
    float g = g_gate[row];
    v.x *= g; v.y *= g; v.z *= g; v.w *= g;
    ((float4*)out)[idx] = v;
}

// ---------------- launch ------------------------------------------------------
extern "C" void kernel_launch(void* const* d_in, const int* in_sizes, int n_in,
                              void* d_out, int out_size)
{
    (void)in_sizes; (void)n_in; (void)out_size;
    const float* q_in   = (const float*)d_in[0];
    const float* kv_in  = (const float*)d_in[1];
    const float* q_w    = (const float*)d_in[2];
    const float* q_b    = (const float*)d_in[3];
    const float* kv_w   = (const float*)d_in[4];
    const float* kv_b   = (const float*)d_in[5];
    const float* proj_w = (const float*)d_in[6];
    const float* proj_b = (const float*)d_in[7];
    const float* sa_w   = (const float*)d_in[8];

    // Q/K/V projections
    gemm_k<0><<<dim3(12, 72), 256>>>(q_in,  q_w,  q_b);
    gemm_k<1><<<dim3(24, 72), 256>>>(kv_in, kv_w, kv_b);

    // flash attention (102400 B dynamic smem)
    cudaFuncSetAttribute(attn_k, cudaFuncAttributeMaxDynamicSharedMemorySize, 102400);
    attn_k<<<dim3(18, 24), 256, 102400>>>();

    // output projection (gathers from g_O)
    gemm_k<2><<<dim3(12, 72), 256>>>(nullptr, proj_w, proj_b);

    // spatial attention branch
    pool_k<<<576, 256>>>();
    conv_k<<<18, 256>>>(sa_w);
    gate_k<<<3456, 256>>>((float*)d_out);
}

// round 2
// speedup vs baseline: 3.0905x; 3.0905x over previous
#include <cuda_runtime.h>
#include <math.h>

#define BATCH 2
#define NTOK  2304
#define CDIM  768
#define NH    12
#define HD    64
#define HWID  48

// ---------------- scratch ----------------
__device__ float g_Q[BATCH*NH*NTOK*HD];
__device__ float g_K[BATCH*NH*NTOK*HD];
__device__ float g_V[BATCH*NH*NTOK*HD];
__device__ float g_O[BATCH*NH*NTOK*HD];
__device__ float g_P[BATCH*NTOK*CDIM];
__device__ float g_pool[BATCH*2*NTOK];
__device__ float g_gate[BATCH*NTOK];

// ---------------- tf32 helpers ----------------
__device__ __forceinline__ unsigned tf32r(float x){
    unsigned u; asm("cvt.rna.tf32.f32 %0, %1;" : "=r"(u) : "f"(x)); return u;
}
__device__ __forceinline__ void mma8(float* d, const unsigned* a, const unsigned* b){
    asm volatile("mma.sync.aligned.m16n8k8.row.col.f32.tf32.tf32.f32 "
        "{%0,%1,%2,%3},{%4,%5,%6,%7},{%8,%9},{%0,%1,%2,%3};"
        : "+f"(d[0]),"+f"(d[1]),"+f"(d[2]),"+f"(d[3])
        : "r"(a[0]),"r"(a[1]),"r"(a[2]),"r"(a[3]),"r"(b[0]),"r"(b[1]));
}

// ---------------- TF32 tensor-core GEMM: C = A @ Bw^T + bias ----------------
// Block 128x128, 8 warps (2m x 4n), warp tile 64x32, k-tile 32, double buffer.
// MODE 0: out -> g_Q[b,h,n,d]; MODE 1: out -> g_K/g_V; MODE 2: A gathered
// from g_O head layout, out -> g_P[b*N+n][c].
template<int MODE>
__global__ __launch_bounds__(256) void gemm_t(const float* __restrict__ A,
                                              const float* __restrict__ Bw,
                                              const float* __restrict__ bias)
{
    extern __shared__ unsigned smg[];
    unsigned* As = smg;               // [2][128][36]
    unsigned* Bs = smg + 2*128*36;    // [2][128][36]
    const int t = threadIdx.x;
    const int lane = t & 31, warp = t >> 5;
    const int g = lane >> 2, tig = lane & 3;
    const int wm = warp >> 2, wn = warp & 3;
    const int m0 = blockIdx.y * 128, n0 = blockIdx.x * 128;

    float acc[4][4][4] = {};
    float4 ra[4], rb[4];

    auto lda = [&](int kt, float4* r){
        #pragma unroll
        for (int p = 0; p < 4; p++){
            int idx = t + p*256, row = idx >> 3, kq = idx & 7;
            int m = m0 + row, k = kt*32 + kq*4;
            if (MODE == 2){
                int b = m >= NTOK; int n = m - b*NTOK;
                r[p] = *(const float4*)&g_O[(((b*NH + (k>>6))*NTOK + n)<<6) + (k&63)];
            } else {
                r[p] = *(const float4*)&A[m*CDIM + k];
            }
        }
    };
    auto ldb = [&](int kt, float4* r){
        #pragma unroll
        for (int p = 0; p < 4; p++){
            int idx = t + p*256, row = idx >> 3, kq = idx & 7;
            r[p] = *(const float4*)&Bw[(n0+row)*CDIM + kt*32 + kq*4];
        }
    };
    auto sts = [&](int buf, const float4* xa, const float4* xb){
        #pragma unroll
        for (int p = 0; p < 4; p++){
            int idx = t + p*256, row = idx >> 3, kq = idx & 7;
            *(uint4*)&As[buf*4608 + row*36 + kq*4] =
                make_uint4(tf32r(xa[p].x), tf32r(xa[p].y), tf32r(xa[p].z), tf32r(xa[p].w));
            *(uint4*)&Bs[buf*4608 + row*36 + kq*4] =
                make_uint4(tf32r(xb[p].x), tf32r(xb[p].y), tf32r(xb[p].z), tf32r(xb[p].w));
        }
    };

    lda(0, ra); ldb(0, rb); sts(0, ra, rb);
    __syncthreads();
    int buf = 0;
    for (int kt = 0; kt < CDIM/32; kt++){
        if (kt < CDIM/32 - 1){ lda(kt+1, ra); ldb(kt+1, rb); }
        const unsigned* Ab = As + buf*4608;
        const unsigned* Bb = Bs + buf*4608;
        #pragma unroll
        for (int kk = 0; kk < 4; kk++){
            unsigned af[4][4];
            #pragma unroll
            for (int i = 0; i < 4; i++){
                int m = wm*64 + i*16;
                af[i][0] = Ab[(m+g  )*36 + kk*8 + tig];
                af[i][1] = Ab[(m+g+8)*36 + kk*8 + tig];
                af[i][2] = Ab[(m+g  )*36 + kk*8 + tig + 4];
                af[i][3] = Ab[(m+g+8)*36 + kk*8 + tig + 4];
            }
            unsigned bf[4][2];
            #pragma unroll
            for (int j = 0; j < 4; j++){
                int n = wn*32 + j*8;
                bf[j][0] = Bb[(n+g)*36 + kk*8 + tig];
                bf[j][1] = Bb[(n+g)*36 + kk*8 + tig + 4];
            }
            #pragma unroll
            for (int i = 0; i < 4; i++)
                #pragma unroll
                for (int j = 0; j < 4; j++)
                    mma8(acc[i][j], af[i], bf[j]);
        }
        if (kt < CDIM/32 - 1) sts(buf^1, ra, rb);
        __syncthreads();
        buf ^= 1;
    }

    // epilogue
    #pragma unroll
    for (int i = 0; i < 4; i++){
        #pragma unroll
        for (int j = 0; j < 4; j++){
            int r0 = m0 + wm*64 + i*16 + g;
            int c0 = n0 + wn*32 + j*8 + 2*tig;
            float b0v = bias[c0], b1v = bias[c0+1];
            #pragma unroll
            for (int hh = 0; hh < 2; hh++){
                int r = r0 + hh*8;
                float2 val = make_float2(acc[i][j][hh*2+0] + b0v,
                                         acc[i][j][hh*2+1] + b1v);
                int b = r >= NTOK; int n = r - b*NTOK;
                if (MODE == 0){
                    *(float2*)&g_Q[(((b*NH + (c0>>6))*NTOK + n)<<6) + (c0&63)] = val;
                } else if (MODE == 1){
                    int ts = c0 >= CDIM; int cc = c0 - ts*CDIM;
                    float* dst = ts ? g_V : g_K;
                    *(float2*)&dst[(((b*NH + (cc>>6))*NTOK + n)<<6) + (cc&63)] = val;
                } else {
                    *(float2*)&g_P[r*CDIM + c0] = val;
                }
            }
        }
    }
}

// ---------------- TF32 tensor-core flash attention ----------------
// Block: 128 queries, 64-key tiles, 8 warps (4 wq x 2 wk).
// S phase: warp = 32q x 32keys; PV phase: warp = 32q x 32d.
// Unnormalized exp accumulate; P round-trips through smem as tf32.
__global__ __launch_bounds__(256) void attn_t()
{
    extern __shared__ unsigned sm[];
    unsigned* Qs = sm;              // [128][68]
    unsigned* Ks = Qs + 128*68;     // [64][68]
    unsigned* Vs = Ks + 64*68;      // [64][68]
    unsigned* Ps = Vs + 64*68;      // [128][68]
    float*   red = (float*)(Ps + 128*68);   // [2][128]

    const int t = threadIdx.x, lane = t & 31, warp = t >> 5;
    const int g = lane >> 2, tig = lane & 3;
    const int wq = warp >> 1, wk = warp & 1;
    const int bh = blockIdx.y, q0 = blockIdx.x * 128;

    const float* Qh = g_Q + (size_t)bh * NTOK * HD;
    const float* Kh = g_K + (size_t)bh * NTOK * HD;
    const float* Vh = g_V + (size_t)bh * NTOK * HD;
    float*       Oh = g_O + (size_t)bh * NTOK * HD;

    #pragma unroll
    for (int p = 0; p < 8; p++){
        int idx = t + p*256, row = idx >> 4, q4 = idx & 15;
        float4 v = *(const float4*)&Qh[(q0+row)*HD + q4*4];
        *(uint4*)&Qs[row*68 + q4*4] =
            make_uint4(tf32r(v.x), tf32r(v.y), tf32r(v.z), tf32r(v.w));
    }

    float accO[2][4][4] = {};
    float lacc[4] = {0.f, 0.f, 0.f, 0.f};

    for (int k0 = 0; k0 < NTOK; k0 += 64){
        __syncthreads();
        #pragma unroll
        for (int p = 0; p < 4; p++){
            int idx = t + p*256, row = idx >> 4, q4 = idx & 15;
            float4 kv = *(const float4*)&Kh[(k0+row)*HD + q4*4];
            *(uint4*)&Ks[row*68 + q4*4] =
                make_uint4(tf32r(kv.x), tf32r(kv.y), tf32r(kv.z), tf32r(kv.w));
            float4 vv = *(const float4*)&Vh[(k0+row)*HD + q4*4];
            *(uint4*)&Vs[row*68 + q4*4] =
                make_uint4(tf32r(vv.x), tf32r(vv.y), tf32r(vv.z), tf32r(vv.w));
        }
        __syncthreads();

        // ---- S = Q K^T ----
        float accS[2][4][4] = {};
        #pragma unroll
        for (int kk = 0; kk < 8; kk++){
            unsigned aq[2][4];
            #pragma unroll
            for (int i = 0; i < 2; i++){
                int m = wq*32 + i*16;
                aq[i][0] = Qs[(m+g  )*68 + kk*8 + tig];
                aq[i][1] = Qs[(m+g+8)*68 + kk*8 + tig];
                aq[i][2] = Qs[(m+g  )*68 + kk*8 + tig + 4];
                aq[i][3] = Qs[(m+g+8)*68 + kk*8 + tig + 4];
            }
            unsigned bk[4][2];
            #pragma unroll
            for (int j = 0; j < 4; j++){
                int n = wk*32 + j*8;
                bk[j][0] = Ks[(n+g)*68 + kk*8 + tig];
                bk[j][1] = Ks[(n+g)*68 + kk*8 + tig + 4];
            }
            #pragma unroll
            for (int i = 0; i < 2; i++)
                #pragma unroll
                for (int j = 0; j < 4; j++)
                    mma8(accS[i][j], aq[i], bk[j]);
        }

        // ---- exp, row-sum partials, write P ----
        #pragma unroll
        for (int i = 0; i < 2; i++){
            #pragma unroll
            for (int j = 0; j < 4; j++){
                int r = wq*32 + i*16 + g;
                int c = wk*32 + j*8 + 2*tig;
                float e0 = __expf(accS[i][j][0] * 0.125f);
                float e1 = __expf(accS[i][j][1] * 0.125f);
                float e2 = __expf(accS[i][j][2] * 0.125f);
                float e3 = __expf(accS[i][j][3] * 0.125f);
                lacc[i*2+0] += e0 + e1;
                lacc[i*2+1] += e2 + e3;
                *(uint2*)&Ps[ r   *68 + c] = make_uint2(tf32r(e0), tf32r(e1));
                *(uint2*)&Ps[(r+8)*68 + c] = make_uint2(tf32r(e2), tf32r(e3));
            }
        }
        __syncthreads();

        // ---- O += P @ V ----
        #pragma unroll
        for (int kk = 0; kk < 8; kk++){
            unsigned ap[2][4];
            #pragma unroll
            for (int i = 0; i < 2; i++){
                int m = wq*32 + i*16;
                ap[i][0] = Ps[(m+g  )*68 + kk*8 + tig];
                ap[i][1] = Ps[(m+g+8)*68 + kk*8 + tig];
                ap[i][2] = Ps[(m+g  )*68 + kk*8 + tig + 4];
                ap[i][3] = Ps[(m+g+8)*68 + kk*8 + tig + 4];
            }
            unsigned bv[4][2];
            #pragma unroll
            for (int j = 0; j < 4; j++){
                int n = wk*32 + j*8;
                bv[j][0] = Vs[(kk*8 + tig  )*68 + n + g];
                bv[j][1] = Vs[(kk*8 + tig+4)*68 + n + g];
            }
            #pragma unroll
            for (int i = 0; i < 2; i++)
                #pragma unroll
                for (int j = 0; j < 4; j++)
                    mma8(accO[i][j], ap[i], bv[j]);
        }
    }

    // ---- reduce row sums: over tig lanes, then across the 2 wk warps ----
    #pragma unroll
    for (int r = 0; r < 4; r++){
        lacc[r] += __shfl_xor_sync(0xffffffffu, lacc[r], 1);
        lacc[r] += __shfl_xor_sync(0xffffffffu, lacc[r], 2);
    }
    if (tig == 0){
        #pragma unroll
        for (int i = 0; i < 2; i++)
            #pragma unroll
            for (int h = 0; h < 2; h++)
                red[wk*128 + wq*32 + i*16 + h*8 + g] = lacc[i*2 + h];
    }
    __syncthreads();

    #pragma unroll
    for (int i = 0; i < 2; i++){
        int r = wq*32 + i*16 + g;
        float inv0 = 1.0f / (red[r]     + red[128 + r]);
        float inv1 = 1.0f / (red[r + 8] + red[128 + r + 8]);
        #pragma unroll
        for (int j = 0; j < 4; j++){
            int c = wk*32 + j*8 + 2*tig;
            *(float2*)&Oh[(q0+r  )*HD + c] =
                make_float2(accO[i][j][0]*inv0, accO[i][j][1]*inv0);
            *(float2*)&Oh[(q0+r+8)*HD + c] =
                make_float2(accO[i][j][2]*inv1, accO[i][j][3]*inv1);
        }
    }
}

// ---------------- channel pooling ----------------
__global__ __launch_bounds__(256) void pool_k()
{
    int wid  = (blockIdx.x * 256 + threadIdx.x) >> 5;
    int lane = threadIdx.x & 31;
    if (wid >= BATCH * NTOK) return;
    const float* row = g_P + (size_t)wid * CDIM;
    float s = 0.f, m = -INFINITY;
    #pragma unroll
    for (int i = 0; i < CDIM/32; i++){
        float v = row[lane + i*32];
        s += v; m = fmaxf(m, v);
    }
    #pragma unroll
    for (int o = 16; o; o >>= 1){
        s += __shfl_xor_sync(0xffffffffu, s, o);
        m = fmaxf(m, __shfl_xor_sync(0xffffffffu, m, o));
    }
    if (lane == 0){
        int b = wid >= NTOK; int n = wid - b*NTOK;
        g_pool[(b*2 + 0)*NTOK + n] = s * (1.0f / CDIM);
        g_pool[(b*2 + 1)*NTOK + n] = m;
    }
}

// ---------------- 7x7x2 conv + sigmoid ----------------
__global__ __launch_bounds__(256) void conv_k(const float* __restrict__ sa_w)
{
    int idx = blockIdx.x * 256 + threadIdx.x;
    if (idx >= BATCH * NTOK) return;
    int b = idx >= NTOK; int n = idx - b*NTOK;
    int hh = n / HWID, ww = n % HWID;
    float acc = 0.f;
    #pragma unroll
    for (int ch = 0; ch < 2; ch++){
        const float* pp = g_pool + (b*2 + ch)*NTOK;
        #pragma unroll
        for (int ki = 0; ki < 7; ki++){
            int y = hh + ki - 3;
            if ((unsigned)y >= (unsigned)HWID) continue;
            #pragma unroll
            for (int kj = 0; kj < 7; kj++){
                int x = ww + kj - 3;
                if ((unsigned)x >= (unsigned)HWID) continue;
                acc += sa_w[ch*49 + ki*7 + kj] * pp[y*HWID + x];
            }
        }
    }
    g_gate[idx] = 1.0f / (1.0f + __expf(-acc));
}

// ---------------- gate multiply ----------------
__global__ __launch_bounds__(256) void gate_k(float* __restrict__ out)
{
    int idx = blockIdx.x * 256 + threadIdx.x;
    float4 v = ((const float4*)g_P)[idx];
    int row = idx / (CDIM/4);
    float gg = g_gate[row];
    v.x *= gg; v.y *= gg; v.z *= gg; v.w *= gg;
    ((float4*)out)[idx] = v;
}

// ---------------- launch ----------------
extern "C" void kernel_launch(void* const* d_in, const int* in_sizes, int n_in,
                              void* d_out, int out_size)
{
    (void)in_sizes; (void)n_in; (void)out_size;
    const float* q_in   = (const float*)d_in[0];
    const float* kv_in  = (const float*)d_in[1];
    const float* q_w    = (const float*)d_in[2];
    const float* q_b    = (const float*)d_in[3];
    const float* kv_w   = (const float*)d_in[4];
    const float* kv_b   = (const float*)d_in[5];
    const float* proj_w = (const float*)d_in[6];
    const float* proj_b = (const float*)d_in[7];
    const float* sa_w   = (const float*)d_in[8];

    const int gemm_smem = 4*128*36*4;      // 73728 B
    const int attn_smem = (128+64+64+128)*68*4 + 2*128*4;  // 105472 B

    cudaFuncSetAttribute(gemm_t<0>, cudaFuncAttributeMaxDynamicSharedMemorySize, gemm_smem);
    cudaFuncSetAttribute(gemm_t<1>, cudaFuncAttributeMaxDynamicSharedMemorySize, gemm_smem);
    cudaFuncSetAttribute(gemm_t<2>, cudaFuncAttributeMaxDynamicSharedMemorySize, gemm_smem);
    cudaFuncSetAttribute(attn_t,    cudaFuncAttributeMaxDynamicSharedMemorySize, attn_smem);

    gemm_t<0><<<dim3( 6, 36), 256, gemm_smem>>>(q_in,  q_w,  q_b);
    gemm_t<1><<<dim3(12, 36), 256, gemm_smem>>>(kv_in, kv_w, kv_b);

    attn_t<<<dim3(18, 24), 256, attn_smem>>>();

    gemm_t<2><<<dim3( 6, 36), 256, gemm_smem>>>(nullptr, proj_w, proj_b);

    pool_k<<<576, 256>>>();
    conv_k<<<18, 256>>>(sa_w);
    gate_k<<<3456, 256>>>((float*)d_out);
}

// round 5
// speedup vs baseline: 4.1527x; 1.3437x over previous
#include <cuda_runtime.h>
#include <cuda_fp16.h>
#include <math.h>
#include <cstdint>

#define BATCH 2
#define NTOK  2304
#define CDIM  768
#define NH    12
#define HD    64
#define HWID  48

// ---------------- scratch ----------------
__device__ float g_Q[BATCH*NH*NTOK*HD];
__device__ float g_K[BATCH*NH*NTOK*HD];
__device__ float g_V[BATCH*NH*NTOK*HD];
__device__ float g_O[BATCH*NH*NTOK*HD];
__device__ float g_P[BATCH*NTOK*CDIM];
__device__ float g_pool[BATCH*2*NTOK];
__device__ float g_gate[BATCH*NTOK];

// ---------------- helpers ----------------
__device__ __forceinline__ unsigned h2(float lo, float hi){
    __half2 v = __floats2half2_rn(lo, hi);
    return reinterpret_cast<unsigned&>(v);
}
__device__ __forceinline__ void mma16(float* d, const unsigned* a, const unsigned* b){
    asm volatile("mma.sync.aligned.m16n8k16.row.col.f32.f16.f16.f32 "
        "{%0,%1,%2,%3},{%4,%5,%6,%7},{%8,%9},{%0,%1,%2,%3};"
        : "+f"(d[0]),"+f"(d[1]),"+f"(d[2]),"+f"(d[3])
        : "r"(a[0]),"r"(a[1]),"r"(a[2]),"r"(a[3]),"r"(b[0]),"r"(b[1]));
}

// ---------------- fp16 tensor-core GEMM: C = A @ Bw^T + bias ----------------
// Block 128x128, 8 warps (2m x 4n), warp tile 64x32, k-tile 32 (2 x k16 mma),
// double-buffered smem (half2, stride 20 h2 = conflict-free), register prefetch.
// MODE 0 -> g_Q[b,h,n,d]; MODE 1 -> g_K/g_V[b,h,n,d]; MODE 2: A from g_O -> g_P.
template<int MODE>
__global__ __launch_bounds__(256) void gemm_h(const float* __restrict__ A,
                                              const float* __restrict__ Bw,
                                              const float* __restrict__ bias)
{
    extern __shared__ __align__(16) unsigned smg[];
    unsigned* As = smg;                 // [2][128][20] half2
    unsigned* Bs = smg + 2*128*20;      // [2][128][20]
    const int t = threadIdx.x;
    const int lane = t & 31, warp = t >> 5;
    const int g = lane >> 2, tig = lane & 3;
    const int wm = warp >> 2, wn = warp & 3;
    const int m0 = blockIdx.y * 128, n0 = blockIdx.x * 128;

    float acc[4][4][4] = {};
    float4 ra[4], rb[4];

    auto ldr = [&](int kt){
        #pragma unroll
        for (int p = 0; p < 4; p++){
            int idx = t + p*256, row = idx >> 3, q = idx & 7;
            int m = m0 + row, k = kt*32 + q*4;
            if (MODE == 2){
                int b = m >= NTOK, n = m - b*NTOK;
                ra[p] = *(const float4*)&g_O[(((b*NH + (k>>6))*NTOK + n) << 6) + (k & 63)];
            } else {
                ra[p] = *(const float4*)&A[m*CDIM + k];
            }
            rb[p] = *(const float4*)&Bw[(n0 + row)*CDIM + k];
        }
    };
    auto sts = [&](int buf){
        #pragma unroll
        for (int p = 0; p < 4; p++){
            int idx = t + p*256, row = idx >> 3, q = idx & 7;
            *(uint2*)&As[buf*2560 + row*20 + 2*q] = make_uint2(h2(ra[p].x, ra[p].y), h2(ra[p].z, ra[p].w));
            *(uint2*)&Bs[buf*2560 + row*20 + 2*q] = make_uint2(h2(rb[p].x, rb[p].y), h2(rb[p].z, rb[p].w));
        }
    };

    ldr(0); sts(0);
    __syncthreads();
    int buf = 0;
    for (int kt = 0; kt < CDIM/32; kt++){
        if (kt < CDIM/32 - 1) ldr(kt + 1);
        const unsigned* Ab = As + buf*2560;
        const unsigned* Bb = Bs + buf*2560;
        #pragma unroll
        for (int kk = 0; kk < 2; kk++){
            unsigned af[4][4], bf[4][2];
            #pragma unroll
            for (int i = 0; i < 4; i++){
                int m = wm*64 + i*16;
                af[i][0] = Ab[(m+g  )*20 + kk*8 + tig];
                af[i][1] = Ab[(m+g+8)*20 + kk*8 + tig];
                af[i][2] = Ab[(m+g  )*20 + kk*8 + tig + 4];
                af[i][3] = Ab[(m+g+8)*20 + kk*8 + tig + 4];
            }
            #pragma unroll
            for (int j = 0; j < 4; j++){
                int n = wn*32 + j*8;
                bf[j][0] = Bb[(n+g)*20 + kk*8 + tig];
                bf[j][1] = Bb[(n+g)*20 + kk*8 + tig + 4];
            }
            #pragma unroll
            for (int i = 0; i < 4; i++)
                #pragma unroll
                for (int j = 0; j < 4; j++)
                    mma16(acc[i][j], af[i], bf[j]);
        }
        if (kt < CDIM/32 - 1) sts(buf ^ 1);
        __syncthreads();
        buf ^= 1;
    }

    // epilogue
    #pragma unroll
    for (int i = 0; i < 4; i++){
        #pragma unroll
        for (int j = 0; j < 4; j++){
            int r0 = m0 + wm*64 + i*16 + g;
            int c0 = n0 + wn*32 + j*8 + 2*tig;
            float b0v = bias[c0], b1v = bias[c0+1];
            #pragma unroll
            for (int hh = 0; hh < 2; hh++){
                int r = r0 + hh*8;
                float2 val = make_float2(acc[i][j][hh*2+0] + b0v,
                                         acc[i][j][hh*2+1] + b1v);
                int b = r >= NTOK; int n = r - b*NTOK;
                if (MODE == 0){
                    *(float2*)&g_Q[(((b*NH + (c0>>6))*NTOK + n) << 6) + (c0 & 63)] = val;
                } else if (MODE == 1){
                    int ts = c0 >= CDIM; int cc = c0 - ts*CDIM;
                    float* dst = ts ? g_V : g_K;
                    *(float2*)&dst[(((b*NH + (cc>>6))*NTOK + n) << 6) + (cc & 63)] = val;
                } else {
                    *(float2*)&g_P[r*CDIM + c0] = val;
                }
            }
        }
    }
}

// ---------------- fp16 tensor-core flash attention ----------------
// 128 queries/CTA, 64-key tiles, 8 warps (4 wq x 2 wk).
// Q fragments hoisted to registers (tile-invariant). K/V double-buffered in
// smem with register prefetch issued one tile ahead. V stored transposed
// (d-major) in smem so PV B-fragments are single half2 LDS.
// P round-trips through the Q smem region (reused) as fp16.
__global__ __launch_bounds__(256) void attn_h()
{
    extern __shared__ __align__(16) unsigned sma[];
    unsigned* Qs = sma;                 // [128][36] h2 (Q, then P)
    unsigned* Ks = Qs + 128*36;         // [2][64][36] h2, row=key, col=d
    unsigned* Vt = Ks + 2*64*36;        // [2][64][36] h2, row=d, col=key
    float*   red = (float*)(Vt + 2*64*36);  // [2][128]

    const int t = threadIdx.x, lane = t & 31, warp = t >> 5;
    const int g = lane >> 2, tig = lane & 3;
    const int wq = warp >> 1, wk = warp & 1;
    const int bh = blockIdx.y, q0 = blockIdx.x * 128;

    const float* Qh = g_Q + (size_t)bh * NTOK * HD;
    const float* Kh = g_K + (size_t)bh * NTOK * HD;
    const float* Vh = g_V + (size_t)bh * NTOK * HD;
    float*       Oh = g_O + (size_t)bh * NTOK * HD;

    // ---- stage Q (half2, stride 36) ----
    #pragma unroll
    for (int p = 0; p < 8; p++){
        int idx = t + p*256, row = idx >> 4, q = idx & 15;
        float4 v = *(const float4*)&Qh[(q0 + row)*HD + q*4];
        *(uint2*)&Qs[row*36 + 2*q] = make_uint2(h2(v.x, v.y), h2(v.z, v.w));
    }

    float4 rk[4], rv[4];
    auto ld_kv = [&](int kt){
        const int k0 = kt * 64;
        #pragma unroll
        for (int p = 0; p < 4; p++){
            int idx = t + p*256, row = idx >> 4, q = idx & 15;
            rk[p] = *(const float4*)&Kh[(k0 + row)*HD + q*4];
            rv[p] = *(const float4*)&Vh[(k0 + row)*HD + q*4];
        }
    };
    auto st_kv = [&](int buf){
        __half* Vtb = (__half*)(Vt + buf*64*36);
        #pragma unroll
        for (int p = 0; p < 4; p++){
            int idx = t + p*256, row = idx >> 4, q = idx & 15;
            *(uint2*)&Ks[buf*64*36 + row*36 + 2*q] = make_uint2(h2(rk[p].x, rk[p].y), h2(rk[p].z, rk[p].w));
            Vtb[(4*q+0)*72 + row] = __float2half_rn(rv[p].x);
            Vtb[(4*q+1)*72 + row] = __float2half_rn(rv[p].y);
            Vtb[(4*q+2)*72 + row] = __float2half_rn(rv[p].z);
            Vtb[(4*q+3)*72 + row] = __float2half_rn(rv[p].w);
        }
    };

    ld_kv(0); st_kv(0);
    __syncthreads();

    // ---- hoist Q fragments (tile-invariant) ----
    unsigned aq[4][2][4];
    #pragma unroll
    for (int kk = 0; kk < 4; kk++)
        #pragma unroll
        for (int i = 0; i < 2; i++){
            int m = wq*32 + i*16;
            aq[kk][i][0] = Qs[(m+g  )*36 + kk*8 + tig];
            aq[kk][i][1] = Qs[(m+g+8)*36 + kk*8 + tig];
            aq[kk][i][2] = Qs[(m+g  )*36 + kk*8 + tig + 4];
            aq[kk][i][3] = Qs[(m+g+8)*36 + kk*8 + tig + 4];
        }
    ld_kv(1);

    float accO[2][4][4] = {};
    float lacc[4] = {0.f, 0.f, 0.f, 0.f};

    for (int kt = 0; kt < NTOK/64; kt++){
        const int buf = kt & 1;
        __syncthreads();   // prev PV done everywhere; K/V[kt] + P region free

        // ---- S = Q K^T ----
        float accS[2][4][4] = {};
        const unsigned* Kb = Ks + buf*64*36;
        #pragma unroll
        for (int kk = 0; kk < 4; kk++){
            unsigned bk[4][2];
            #pragma unroll
            for (int j = 0; j < 4; j++){
                int n = wk*32 + j*8;
                bk[j][0] = Kb[(n+g)*36 + kk*8 + tig];
                bk[j][1] = Kb[(n+g)*36 + kk*8 + tig + 4];
            }
            #pragma unroll
            for (int i = 0; i < 2; i++)
                #pragma unroll
                for (int j = 0; j < 4; j++)
                    mma16(accS[i][j], aq[kk][i], bk[j]);
        }

        // ---- exp, row-sum partials, write P (fp16, into Qs region) ----
        #pragma unroll
        for (int i = 0; i < 2; i++){
            #pragma unroll
            for (int j = 0; j < 4; j++){
                int r = wq*32 + i*16 + g;
                int ch = wk*16 + j*4 + tig;       // half2 col
                float e0 = __expf(accS[i][j][0] * 0.125f);
                float e1 = __expf(accS[i][j][1] * 0.125f);
                float e2 = __expf(accS[i][j][2] * 0.125f);
                float e3 = __expf(accS[i][j][3] * 0.125f);
                lacc[i*2+0] += e0 + e1;
                lacc[i*2+1] += e2 + e3;
                Qs[ r   *36 + ch] = h2(e0, e1);
                Qs[(r+8)*36 + ch] = h2(e2, e3);
            }
        }

        // ---- prefetch/stage next K/V ----
        if (kt < NTOK/64 - 1){
            st_kv(buf ^ 1);                       // data for tile kt+1
            if (kt < NTOK/64 - 2) ld_kv(kt + 2);  // issue LDGs for tile kt+2
        }
        __syncthreads();   // P visible; stores done

        // ---- O += P @ V ----
        const unsigned* Vb = Vt + buf*64*36;
        #pragma unroll
        for (int kk = 0; kk < 4; kk++){
            unsigned ap[2][4], bv[4][2];
            #pragma unroll
            for (int i = 0; i < 2; i++){
                int m = wq*32 + i*16;
                ap[i][0] = Qs[(m+g  )*36 + kk*8 + tig];
                ap[i][1] = Qs[(m+g+8)*36 + kk*8 + tig];
                ap[i][2] = Qs[(m+g  )*36 + kk*8 + tig + 4];
                ap[i][3] = Qs[(m+g+8)*36 + kk*8 + tig + 4];
            }
            #pragma unroll
            for (int j = 0; j < 4; j++){
                int n = wk*32 + j*8;
                bv[j][0] = Vb[(n+g)*36 + kk*8 + tig];
                bv[j][1] = Vb[(n+g)*36 + kk*8 + tig + 4];
            }
            #pragma unroll
            for (int i = 0; i < 2; i++)
                #pragma unroll
                for (int j = 0; j < 4; j++)
                    mma16(accO[i][j], ap[i], bv[j]);
        }
    }

    // ---- reduce row sums: tig lanes, then the 2 wk warps ----
    #pragma unroll
    for (int r = 0; r < 4; r++){
        lacc[r] += __shfl_xor_sync(0xffffffffu, lacc[r], 1);
        lacc[r] += __shfl_xor_sync(0xffffffffu, lacc[r], 2);
    }
    if (tig == 0){
        #pragma unroll
        for (int i = 0; i < 2; i++)
            #pragma unroll
            for (int hh = 0; hh < 2; hh++)
                red[wk*128 + wq*32 + i*16 + hh*8 + g] = lacc[i*2 + hh];
    }
    __syncthreads();

    #pragma unroll
    for (int i = 0; i < 2; i++){
        int r = wq*32 + i*16 + g;
        float inv0 = 1.0f / (red[r]     + red[128 + r]);
        float inv1 = 1.0f / (red[r + 8] + red[128 + r + 8]);
        #pragma unroll
        for (int j = 0; j < 4; j++){
            int c = wk*32 + j*8 + 2*tig;
            *(float2*)&Oh[(q0+r  )*HD + c] =
                make_float2(accO[i][j][0]*inv0, accO[i][j][1]*inv0);
            *(float2*)&Oh[(q0+r+8)*HD + c] =
                make_float2(accO[i][j][2]*inv1, accO[i][j][3]*inv1);
        }
    }
}

// ---------------- channel pooling ----------------
__global__ __launch_bounds__(256) void pool_k()
{
    int wid  = (blockIdx.x * 256 + threadIdx.x) >> 5;
    int lane = threadIdx.x & 31;
    if (wid >= BATCH * NTOK) return;
    const float* row = g_P + (size_t)wid * CDIM;
    float s = 0.f, m = -INFINITY;
    #pragma unroll
    for (int i = 0; i < CDIM/32; i++){
        float v = row[lane + i*32];
        s += v; m = fmaxf(m, v);
    }
    #pragma unroll
    for (int o = 16; o; o >>= 1){
        s += __shfl_xor_sync(0xffffffffu, s, o);
        m = fmaxf(m, __shfl_xor_sync(0xffffffffu, m, o));
    }
    if (lane == 0){
        int b = wid >= NTOK; int n = wid - b*NTOK;
        g_pool[(b*2 + 0)*NTOK + n] = s * (1.0f / CDIM);
        g_pool[(b*2 + 1)*NTOK + n] = m;
    }
}

// ---------------- 7x7x2 conv + sigmoid ----------------
__global__ __launch_bounds__(256) void conv_k(const float* __restrict__ sa_w)
{
    int idx = blockIdx.x * 256 + threadIdx.x;
    if (idx >= BATCH * NTOK) return;
    int b = idx >= NTOK; int n = idx - b*NTOK;
    int hh = n / HWID, ww = n % HWID;
    float acc = 0.f;
    #pragma unroll
    for (int ch = 0; ch < 2; ch++){
        const float* pp = g_pool + (b*2 + ch)*NTOK;
        #pragma unroll
        for (int ki = 0; ki < 7; ki++){
            int y = hh + ki - 3;
            if ((unsigned)y >= (unsigned)HWID) continue;
            #pragma unroll
            for (int kj = 0; kj < 7; kj++){
                int x = ww + kj - 3;
                if ((unsigned)x >= (unsigned)HWID) continue;
                acc += sa_w[ch*49 + ki*7 + kj] * pp[y*HWID + x];
            }
        }
    }
    g_gate[idx] = 1.0f / (1.0f + __expf(-acc));
}

// ---------------- gate multiply ----------------
__global__ __launch_bounds__(256) void gate_k(float* __restrict__ out)
{
    int idx = blockIdx.x * 256 + threadIdx.x;
    float4 v = ((const float4*)g_P)[idx];
    int row = idx / (CDIM/4);
    float gg = g_gate[row];
    v.x *= gg; v.y *= gg; v.z *= gg; v.w *= gg;
    ((float4*)out)[idx] = v;
}

// ---------------- launch ----------------
extern "C" void kernel_launch(void* const* d_in, const int* in_sizes, int n_in,
                              void* d_out, int out_size)
{
    (void)in_sizes; (void)n_in; (void)out_size;
    const float* q_in   = (const float*)d_in[0];
    const float* kv_in  = (const float*)d_in[1];
    const float* q_w    = (const float*)d_in[2];
    const float* q_b    = (const float*)d_in[3];
    const float* kv_w   = (const float*)d_in[4];
    const float* kv_b   = (const float*)d_in[5];
    const float* proj_w = (const float*)d_in[6];
    const float* proj_b = (const float*)d_in[7];
    const float* sa_w   = (const float*)d_in[8];

    const int gemm_smem = 2 * 2*128*20 * 4;                 // 40960 B
    const int attn_smem = (128*36 + 4*64*36) * 4 + 2*128*4; // 56320 B

    cudaFuncSetAttribute(attn_h, cudaFuncAttributeMaxDynamicSharedMemorySize, attn_smem);

    gemm_h<0><<<dim3( 6, 36), 256, gemm_smem>>>(q_in,  q_w,  q_b);
    gemm_h<1><<<dim3(12, 36), 256, gemm_smem>>>(kv_in, kv_w, kv_b);

    attn_h<<<dim3(18, 24), 256, attn_smem>>>();

    gemm_h<2><<<dim3( 6, 36), 256, gemm_smem>>>(nullptr, proj_w, proj_b);

    pool_k<<<576, 256>>>();
    conv_k<<<18, 256>>>(sa_w);
    gate_k<<<3456, 256>>>((float*)d_out);
}

// round 6
// speedup vs baseline: 5.1288x; 1.2351x over previous
#include <cuda_runtime.h>
#include <cuda_fp16.h>
#include <math.h>
#include <cstdint>

#define BATCH 2
#define NTOK  2304
#define CDIM  768
#define NH    12
#define HD    64
#define HWID  48
#define NELEM (BATCH*NH*NTOK*HD)

// ---------------- scratch (fp16 operands, fp32 final) ----------------
__device__ __half g_qinh [BATCH*NTOK*CDIM];
__device__ __half g_kvinh[BATCH*NTOK*CDIM];
__device__ __half g_qwh [CDIM*CDIM];
__device__ __half g_kvwh[2*CDIM*CDIM];
__device__ __half g_pwh [CDIM*CDIM];
__device__ __half g_Qh [NELEM];          // [bh][n][d]
__device__ __half g_Kh [NELEM];          // [bh][n][d]
__device__ __half g_Vth[NELEM];          // [bh][d][n]  (transposed)
__device__ __half g_Oh [NELEM];          // [bh][n][d]
__device__ float  g_P[BATCH*NTOK*CDIM];
__device__ float  g_pool[BATCH*2*NTOK];
__device__ float  g_gate[BATCH*NTOK];

// ---------------- helpers ----------------
__device__ __forceinline__ uint32_t s2u(const void* p){
    uint32_t a;
    asm("{ .reg .u64 t; cvta.to.shared.u64 t, %1; cvt.u32.u64 %0, t; }" : "=r"(a) : "l"(p));
    return a;
}
__device__ __forceinline__ unsigned h2(float lo, float hi){
    __half2 v = __floats2half2_rn(lo, hi);
    return reinterpret_cast<unsigned&>(v);
}
__device__ __forceinline__ void mma16(float* d, const unsigned* a, const unsigned* b){
    asm volatile("mma.sync.aligned.m16n8k16.row.col.f32.f16.f16.f32 "
        "{%0,%1,%2,%3},{%4,%5,%6,%7},{%8,%9},{%0,%1,%2,%3};"
        : "+f"(d[0]),"+f"(d[1]),"+f"(d[2]),"+f"(d[3])
        : "r"(a[0]),"r"(a[1]),"r"(a[2]),"r"(a[3]),"r"(b[0]),"r"(b[1]));
}
__device__ __forceinline__ void cpa(uint32_t s, const void* g){
    asm volatile("cp.async.cg.shared.global [%0], [%1], 16;" :: "r"(s), "l"(g));
}
__device__ __forceinline__ void ldm4(unsigned* r, uint32_t a){
    asm volatile("ldmatrix.sync.aligned.m8n8.x4.shared.b16 {%0,%1,%2,%3}, [%4];"
        : "=r"(r[0]),"=r"(r[1]),"=r"(r[2]),"=r"(r[3]) : "r"(a));
}
#define CP_COMMIT() asm volatile("cp.async.commit_group;" ::: "memory")
#define CP_WAIT0()  asm volatile("cp.async.wait_group 0;" ::: "memory")
#define CP_WAIT1()  asm volatile("cp.async.wait_group 1;" ::: "memory")

// ---------------- one-shot fp32 -> fp16 conversion ----------------
__global__ __launch_bounds__(256) void cvt_all(const float* __restrict__ qi,
                                               const float* __restrict__ kvi,
                                               const float* __restrict__ qw,
                                               const float* __restrict__ kvw,
                                               const float* __restrict__ pw)
{
    int u = blockIdx.x*256 + threadIdx.x;       // float4 units
    const int S0 = BATCH*NTOK*CDIM/4;           // 884736
    const int S1 = S0*2;
    const int S2 = S1 + CDIM*CDIM/4;
    const int S3 = S2 + 2*CDIM*CDIM/4;
    const int S4 = S3 + CDIM*CDIM/4;
    if (u >= S4) return;
    const float* src; __half* dst; int off;
    if      (u < S0){ src = qi;  dst = g_qinh;  off = u; }
    else if (u < S1){ src = kvi; dst = g_kvinh; off = u - S0; }
    else if (u < S2){ src = qw;  dst = g_qwh;   off = u - S1; }
    else if (u < S3){ src = kvw; dst = g_kvwh;  off = u - S2; }
    else            { src = pw;  dst = g_pwh;   off = u - S3; }
    float4 v = ((const float4*)src)[off];
    ((uint2*)dst)[off] = make_uint2(h2(v.x, v.y), h2(v.z, v.w));
}

// ---------------- fp16 GEMM, cp.async 3-stage + ldmatrix ----------------
// 128x128 CTA, 8 warps (2m x 4n), warp 64x32, k-tile 32 halves.
// Stage = [A 128x40B-rows (80B stride)][B same] = 20480 B; 3 stages.
// MODE 0: fused QKV (grid.x 18: 0-5 Q, 6-17 KV); MODE 2: proj (A from g_Oh -> g_P).
template<int MODE>
__global__ __launch_bounds__(256,2) void gemm_h2(const float* __restrict__ bias0,
                                                 const float* __restrict__ bias1)
{
    extern __shared__ __align__(16) char dsm[];
    const uint32_t sbase = s2u(dsm);
    const int t = threadIdx.x, lane = t & 31, warp = t >> 5;
    const int g = lane >> 2, tig = lane & 3;
    const int wm = warp >> 2, wn = warp & 3;
    const int m0 = blockIdx.y * 128;
    const int n0g = blockIdx.x * 128;

    const __half* Ah = nullptr; const __half* Wh;
    if (MODE == 0){
        if (n0g < CDIM){ Ah = g_qinh;  Wh = g_qwh  + n0g*CDIM; }
        else           { Ah = g_kvinh; Wh = g_kvwh + (n0g - CDIM)*CDIM; }
    } else {
        Wh = g_pwh + n0g*CDIM;
    }

    auto issue = [&](int kt, int stg){
        const uint32_t so = sbase + (uint32_t)stg*20480u;
        #pragma unroll
        for (int p = 0; p < 2; p++){
            int ch = t + p*256;
            int row = ch & 127, c = ch >> 7;
            const __half* ga;
            if (MODE == 2){
                int m = m0 + row; int b = m >= NTOK, n = m - b*NTOK;
                int k = kt*32 + c*8;
                ga = g_Oh + (((b*NH + (k>>6))*NTOK + n) << 6) + (k & 63);
            } else {
                ga = Ah + (m0 + row)*CDIM + kt*32 + c*8;
            }
            cpa(so + row*80 + c*16, ga);
            cpa(so + 10240 + row*80 + c*16, Wh + row*CDIM + kt*32 + c*8);
        }
        CP_COMMIT();
    };

    float acc[4][4][4] = {};
    issue(0, 0); issue(1, 1);

    const uint32_t aAddr = sbase + (wm*64 + (lane & 15))*80 + (lane>>4)*16;
    const uint32_t bAddr = sbase + 10240
                         + (wn*32 + (lane & 7) + ((lane>>4)<<3))*80 + ((lane>>3)&1)*16;

    int stg = 0, stg2 = 2;
    for (int kt = 0; kt < CDIM/32; kt++){
        CP_WAIT1();
        __syncthreads();
        if (kt + 2 < CDIM/32){ issue(kt+2, stg2); stg2 = (stg2 == 2) ? 0 : stg2 + 1; }
        const uint32_t so = (uint32_t)stg*20480u;
        #pragma unroll
        for (int kk = 0; kk < 2; kk++){
            unsigned af[4][4], bf[2][4];
            #pragma unroll
            for (int i = 0; i < 4; i++) ldm4(af[i], aAddr + so + i*1280 + kk*32);
            #pragma unroll
            for (int jp = 0; jp < 2; jp++) ldm4(bf[jp], bAddr + so + jp*1280 + kk*32);
            #pragma unroll
            for (int i = 0; i < 4; i++)
                #pragma unroll
                for (int j = 0; j < 4; j++)
                    mma16(acc[i][j], af[i], &bf[j>>1][(j&1)*2]);
        }
        stg = (stg == 2) ? 0 : stg + 1;
    }

    // epilogue
    #pragma unroll
    for (int i = 0; i < 4; i++){
        #pragma unroll
        for (int j = 0; j < 4; j++){
            int r0 = m0 + wm*64 + i*16 + g;
            int c0g = n0g + wn*32 + j*8 + 2*tig;
            #pragma unroll
            for (int hh = 0; hh < 2; hh++){
                int r = r0 + hh*8;
                int b = r >= NTOK, n = r - b*NTOK;
                float x = acc[i][j][hh*2+0], y = acc[i][j][hh*2+1];
                if (MODE == 2){
                    x += bias0[c0g]; y += bias0[c0g+1];
                    *(float2*)&g_P[r*CDIM + c0g] = make_float2(x, y);
                } else {
                    if (c0g < CDIM){
                        x += bias0[c0g]; y += bias0[c0g+1];
                        *(__half2*)&g_Qh[(((b*NH + (c0g>>6))*NTOK + n) << 6) + (c0g & 63)] =
                            __floats2half2_rn(x, y);
                    } else {
                        int ck = c0g - CDIM;
                        x += bias1[ck]; y += bias1[ck+1];
                        if (ck < CDIM){
                            *(__half2*)&g_Kh[(((b*NH + (ck>>6))*NTOK + n) << 6) + (ck & 63)] =
                                __floats2half2_rn(x, y);
                        } else {
                            int cv = ck - CDIM;
                            __half* vb = &g_Vth[((b*NH + (cv>>6))*HD + (cv & 63))*NTOK + n];
                            vb[0]    = __float2half_rn(x);
                            vb[NTOK] = __float2half_rn(y);
                        }
                    }
                }
            }
        }
    }
}

// ---------------- fp16 flash attention, cp.async + ldmatrix ----------------
// 128 q/CTA, 64-key tiles, 8 warps (4 wq x 2 wk). Q frags hoisted to regs;
// Q smem region reused as P. K/V double-buffered, prefetched 1 tile ahead.
// smem: Q/P [128 x 144B] | K [2][64 x 144B] | V^T [2][64 x 144B] | red [2][128]f
__global__ __launch_bounds__(256,2) void attn_h2()
{
    extern __shared__ __align__(16) char dsm[];
    const uint32_t sbase = s2u(dsm);
    unsigned* Qp = (unsigned*)dsm;
    float* red = (float*)(dsm + 55296);
    const int t = threadIdx.x, lane = t & 31, warp = t >> 5;
    const int g = lane >> 2, tig = lane & 3;
    const int wq = warp >> 1, wk = warp & 1;
    const int bh = blockIdx.y, q0 = blockIdx.x * 128;

    const __half* Qg = g_Qh  + (size_t)bh * NTOK * HD;
    const __half* Kg = g_Kh  + (size_t)bh * NTOK * HD;
    const __half* Vg = g_Vth + (size_t)bh * HD * NTOK;
    __half*       Og = g_Oh  + (size_t)bh * NTOK * HD;

    // Q: 1024 16B chunks
    #pragma unroll
    for (int p = 0; p < 4; p++){
        int ch = t + p*256;
        int row = ch >> 3, c = ch & 7;
        cpa(sbase + row*144 + c*16, Qg + (q0 + row)*HD + c*8);
    }
    CP_COMMIT();

    auto issueKV = [&](int kt, int buf){
        const int k0 = kt * 64;
        #pragma unroll
        for (int p = 0; p < 2; p++){
            int ch = t + p*256;
            int row = ch >> 3, c = ch & 7;
            cpa(sbase + 18432 + buf*9216 + row*144 + c*16, Kg + (k0 + row)*HD + c*8);
            cpa(sbase + 36864 + buf*9216 + row*144 + c*16, Vg + row*NTOK + k0 + c*8);
        }
        CP_COMMIT();
    };

    issueKV(0, 0);
    CP_WAIT0();
    __syncthreads();

    const uint32_t qAddr = sbase + (wq*32 + (lane & 15))*144 + (lane>>4)*16;
    const uint32_t bOff  = ((lane & 7) + ((lane>>4)<<3))*144 + ((lane>>3)&1)*16;
    const uint32_t kAddr = sbase + 18432 + wk*32*144 + bOff;
    const uint32_t vAddr = sbase + 36864 + wk*32*144 + bOff;

    // hoist Q fragments (tile-invariant)
    unsigned aq[4][2][4];
    #pragma unroll
    for (int kk = 0; kk < 4; kk++)
        #pragma unroll
        for (int i = 0; i < 2; i++)
            ldm4(aq[kk][i], qAddr + i*2304 + kk*32);

    float accO[2][4][4] = {};
    float lacc[4] = {0.f, 0.f, 0.f, 0.f};

    for (int kt = 0; kt < NTOK/64; kt++){
        const int buf = kt & 1;
        if (kt){
            CP_WAIT0();
            __syncthreads();   // tile kt ready; all PV(kt-1) done (P region free)
        }

        // ---- S = Q K^T ----
        float accS[2][4][4] = {};
        #pragma unroll
        for (int kk = 0; kk < 4; kk++){
            unsigned bk[2][4];
            #pragma unroll
            for (int jp = 0; jp < 2; jp++) ldm4(bk[jp], kAddr + buf*9216 + jp*2304 + kk*32);
            #pragma unroll
            for (int i = 0; i < 2; i++)
                #pragma unroll
                for (int j = 0; j < 4; j++)
                    mma16(accS[i][j], aq[kk][i], &bk[j>>1][(j&1)*2]);
        }

        // ---- exp, row-sum partials, write P (fp16, Q region) ----
        #pragma unroll
        for (int i = 0; i < 2; i++){
            #pragma unroll
            for (int j = 0; j < 4; j++){
                int r = wq*32 + i*16 + g;
                int ch = wk*16 + j*4 + tig;
                float e0 = __expf(accS[i][j][0] * 0.125f);
                float e1 = __expf(accS[i][j][1] * 0.125f);
                float e2 = __expf(accS[i][j][2] * 0.125f);
                float e3 = __expf(accS[i][j][3] * 0.125f);
                lacc[i*2+0] += e0 + e1;
                lacc[i*2+1] += e2 + e3;
                Qp[ r   *36 + ch] = h2(e0, e1);
                Qp[(r+8)*36 + ch] = h2(e2, e3);
            }
        }
        __syncthreads();       // P visible
        if (kt + 1 < NTOK/64) issueKV(kt+1, buf^1);

        // ---- O += P @ V ----
        #pragma unroll
        for (int kk = 0; kk < 4; kk++){
            unsigned ap[2][4], bv[2][4];
            #pragma unroll
            for (int i = 0; i < 2; i++) ldm4(ap[i], qAddr + i*2304 + kk*32);
            #pragma unroll
            for (int jp = 0; jp < 2; jp++) ldm4(bv[jp], vAddr + buf*9216 + jp*2304 + kk*32);
            #pragma unroll
            for (int i = 0; i < 2; i++)
                #pragma unroll
                for (int j = 0; j < 4; j++)
                    mma16(accO[i][j], ap[i], &bv[j>>1][(j&1)*2]);
        }
    }

    // ---- reduce row sums: tig lanes, then the 2 wk warps ----
    #pragma unroll
    for (int r = 0; r < 4; r++){
        lacc[r] += __shfl_xor_sync(0xffffffffu, lacc[r], 1);
        lacc[r] += __shfl_xor_sync(0xffffffffu, lacc[r], 2);
    }
    if (tig == 0){
        #pragma unroll
        for (int i = 0; i < 2; i++)
            #pragma unroll
            for (int hh = 0; hh < 2; hh++)
                red[wk*128 + wq*32 + i*16 + hh*8 + g] = lacc[i*2 + hh];
    }
    __syncthreads();

    #pragma unroll
    for (int i = 0; i < 2; i++){
        int r = wq*32 + i*16 + g;
        float inv0 = 1.0f / (red[r]     + red[128 + r]);
        float inv1 = 1.0f / (red[r + 8] + red[128 + r + 8]);
        #pragma unroll
        for (int j = 0; j < 4; j++){
            int c = wk*32 + j*8 + 2*tig;
            *(__half2*)&Og[(q0+r  )*HD + c] =
                __floats2half2_rn(accO[i][j][0]*inv0, accO[i][j][1]*inv0);
            *(__half2*)&Og[(q0+r+8)*HD + c] =
                __floats2half2_rn(accO[i][j][2]*inv1, accO[i][j][3]*inv1);
        }
    }
}

// ---------------- channel pooling ----------------
__global__ __launch_bounds__(256) void pool_k()
{
    int wid  = (blockIdx.x * 256 + threadIdx.x) >> 5;
    int lane = threadIdx.x & 31;
    if (wid >= BATCH * NTOK) return;
    const float* row = g_P + (size_t)wid * CDIM;
    float s = 0.f, m = -INFINITY;
    #pragma unroll
    for (int i = 0; i < CDIM/32; i++){
        float v = row[lane + i*32];
        s += v; m = fmaxf(m, v);
    }
    #pragma unroll
    for (int o = 16; o; o >>= 1){
        s += __shfl_xor_sync(0xffffffffu, s, o);
        m = fmaxf(m, __shfl_xor_sync(0xffffffffu, m, o));
    }
    if (lane == 0){
        int b = wid >= NTOK; int n = wid - b*NTOK;
        g_pool[(b*2 + 0)*NTOK + n] = s * (1.0f / CDIM);
        g_pool[(b*2 + 1)*NTOK + n] = m;
    }
}

// ---------------- 7x7x2 conv + sigmoid ----------------
__global__ __launch_bounds__(256) void conv_k(const float* __restrict__ sa_w)
{
    int idx = blockIdx.x * 256 + threadIdx.x;
    if (idx >= BATCH * NTOK) return;
    int b = idx >= NTOK; int n = idx - b*NTOK;
    int hh = n / HWID, ww = n % HWID;
    float acc = 0.f;
    #pragma unroll
    for (int ch = 0; ch < 2; ch++){
        const float* pp = g_pool + (b*2 + ch)*NTOK;
        #pragma unroll
        for (int ki = 0; ki < 7; ki++){
            int y = hh + ki - 3;
            if ((unsigned)y >= (unsigned)HWID) continue;
            #pragma unroll
            for (int kj = 0; kj < 7; kj++){
                int x = ww + kj - 3;
                if ((unsigned)x >= (unsigned)HWID) continue;
                acc += sa_w[ch*49 + ki*7 + kj] * pp[y*HWID + x];
            }
        }
    }
    g_gate[idx] = 1.0f / (1.0f + __expf(-acc));
}

// ---------------- gate multiply ----------------
__global__ __launch_bounds__(256) void gate_k(float* __restrict__ out)
{
    int idx = blockIdx.x * 256 + threadIdx.x;
    float4 v = ((const float4*)g_P)[idx];
    int row = idx / (CDIM/4);
    float gg = g_gate[row];
    v.x *= gg; v.y *= gg; v.z *= gg; v.w *= gg;
    ((float4*)out)[idx] = v;
}

// ---------------- launch ----------------
extern "C" void kernel_launch(void* const* d_in, const int* in_sizes, int n_in,
                              void* d_out, int out_size)
{
    (void)in_sizes; (void)n_in; (void)out_size;
    const float* q_in   = (const float*)d_in[0];
    const float* kv_in  = (const float*)d_in[1];
    const float* q_w    = (const float*)d_in[2];
    const float* q_b    = (const float*)d_in[3];
    const float* kv_w   = (const float*)d_in[4];
    const float* kv_b   = (const float*)d_in[5];
    const float* proj_w = (const float*)d_in[6];
    const float* proj_b = (const float*)d_in[7];
    const float* sa_w   = (const float*)d_in[8];

    const int gemm_smem = 3 * 20480;   // 61440
    const int attn_smem = 56320;
    cudaFuncSetAttribute(gemm_h2<0>, cudaFuncAttributeMaxDynamicSharedMemorySize, gemm_smem);
    cudaFuncSetAttribute(gemm_h2<2>, cudaFuncAttributeMaxDynamicSharedMemorySize, gemm_smem);
    cudaFuncSetAttribute(attn_h2,    cudaFuncAttributeMaxDynamicSharedMemorySize, attn_smem);

    cvt_all<<<9216, 256>>>(q_in, kv_in, q_w, kv_w, proj_w);

    gemm_h2<0><<<dim3(18, 36), 256, gemm_smem>>>(q_b, kv_b);     // fused Q + KV proj

    attn_h2<<<dim3(18, 24), 256, attn_smem>>>();

    gemm_h2<2><<<dim3( 6, 36), 256, gemm_smem>>>(proj_b, nullptr);

    pool_k<<<576, 256>>>();
    conv_k<<<18, 256>>>(sa_w);
    gate_k<<<3456, 256>>>((float*)d_out);
}